// round 5
// baseline (speedup 1.0000x reference)
#include <cuda_runtime.h>
#include <cstdint>

#define MAXB  1024
#define EPS   1e-5f
#define SLOPE 0.01f

// ---------------- static device scratch (no allocations allowed) ----------------
__device__ __align__(16) float d_A [MAXB * 128];  // per-graph sum of a_e
__device__ __align__(16) float d_gx[MAXB * 64];   // per-graph sum of x
__device__            int   d_cnt[MAXB];          // edges per graph
__device__ __align__(16) float d_Q [128];         // sum of a^2 over all edges
__device__ __align__(16) float d_s1[128], d_t2[128];
__device__ __align__(16) float d_S1[128], d_Q1[128], d_S2[128], d_Q2[128];
__device__ __align__(16) float d_a1[MAXB * 128], d_a2[MAXB * 128];
__device__            int   d_f_e64, d_f_b64;     // 1 if int64-encoded, else int32

// ---------------- helpers ----------------
__device__ __forceinline__ void red4(float* p, float4 v) {
    asm volatile("red.global.add.v4.f32 [%0], {%1,%2,%3,%4};"
                 :: "l"(p), "f"(v.x), "f"(v.y), "f"(v.z), "f"(v.w) : "memory");
}

#define DUP2(d, f)        asm("mov.b64 %0, {%1, %1};" : "=l"(d) : "f"(f))
#define UNPK2(lo, hi, v)  asm("mov.b64 {%0, %1}, %2;" : "=f"(lo), "=f"(hi) : "l"(v))
#define PK2(d, lo, hi)    asm("mov.b64 %0, {%1, %2};" : "=l"(d) : "f"(lo), "f"(hi))
#define FFMA2(acc, a, b)  asm("fma.rn.f32x2 %0, %1, %2, %0;" : "+l"(acc) : "l"(a), "l"(b))

__device__ __forceinline__ long long ldix(const void* p, long long i, int is64) {
    return is64 ? ((const long long*)p)[i] : (long long)((const int*)p)[i];
}

__device__ __forceinline__ float leaky(float z) { return z >= 0.f ? z : SLOPE * z; }

// ---------------- K0: zero scratch + detect index width ----------------
__global__ void k_init(const void* eidx, const void* bat,
                       long long e2w, long long nw) {
    int idx = blockIdx.x * blockDim.x + threadIdx.x;
    int stride = gridDim.x * blockDim.x;
    for (int i = idx; i < MAXB * 128; i += stride) d_A[i] = 0.f;
    for (int i = idx; i < MAXB * 64;  i += stride) d_gx[i] = 0.f;
    for (int i = idx; i < MAXB;       i += stride) d_cnt[i] = 0;
    for (int i = idx; i < 128;        i += stride) {
        d_Q[i] = 0.f; d_S1[i] = 0.f; d_Q1[i] = 0.f; d_S2[i] = 0.f; d_Q2[i] = 0.f;
    }
    // detection: warp 0 of block 0 samples odd 32-bit words; int64 => high halves all 0
    if (blockIdx.x == 0 && threadIdx.x < 32) {
        const unsigned* we = (const unsigned*)eidx;
        const unsigned* wb = (const unsigned*)bat;
        int lane = threadIdx.x;
        int nz_e = 0, nz_b = 0;
        long long se = e2w / 64; if (se < 2) se = 2;
        long long sb = nw  / 64; if (sb < 2) sb = 2;
        for (int s = 0; s < 2; ++s) {
            long long k = lane * 2 + s;
            long long pe = (k * se) | 1; if (pe >= e2w) pe = 1;
            long long pb = (k * sb) | 1; if (pb >= nw)  pb = 1;
            if (we[pe] != 0u) nz_e++;
            if (wb[pb] != 0u) nz_b++;
        }
        for (int o = 16; o > 0; o >>= 1) {
            nz_e += __shfl_xor_sync(0xffffffffu, nz_e, o);
            nz_b += __shfl_xor_sync(0xffffffffu, nz_b, o);
        }
        if (lane == 0) {
            d_f_e64 = (nz_e < 8) ? 1 : 0;
            d_f_b64 = (nz_b < 8) ? 1 : 0;
        }
    }
}

// ---------------- K1: fused gather + GEMM1 + leaky + scatter(A,Q,cnt) ----------------
// Block: 256 threads, 128 edges. Thread (tx=tid&15, ty=tid>>4):
// 8 edges (ty*8..+7), 8 cols ({4tx..4tx+3} and {64+4tx..+3}).
__global__ __launch_bounds__(256, 2)
void k_edge(const float* __restrict__ x, const void* __restrict__ eidx,
            const float* __restrict__ ea, const void* __restrict__ bat,
            const float* __restrict__ W1a, const float* __restrict__ b1a,
            long long E) {
    __shared__ float As[32 * 128];
    __shared__ float Ws[32 * 128];
    __shared__ int   srow[128];
    __shared__ int   sg[128];

    const int tid = threadIdx.x;
    const long long e0 = (long long)blockIdx.x * 128;
    const int e64 = d_f_e64, b64 = d_f_b64;

    if (tid < 128) {
        long long e = e0 + tid;
        int r = 0, g = 0;
        if (e < E) {
            r = (int)ldix(eidx, e, e64);
            long long cc = ldix(eidx, E + e, e64);
            g = (int)ldix(bat, cc, b64);
        }
        srow[tid] = r;
        sg[tid]   = g;
    }

    const int tx = tid & 15, ty = tid >> 4;
    const int c0 = 4 * tx, c1 = 64 + 4 * tx;

    unsigned long long acc[8][4];
    {
        float4 bb0 = *(const float4*)(b1a + c0);
        float4 bb1 = *(const float4*)(b1a + c1);
        unsigned long long p0, p1, p2, p3;
        PK2(p0, bb0.x, bb0.y); PK2(p1, bb0.z, bb0.w);
        PK2(p2, bb1.x, bb1.y); PK2(p3, bb1.z, bb1.w);
        #pragma unroll
        for (int e = 0; e < 8; ++e) {
            acc[e][0] = p0; acc[e][1] = p1; acc[e][2] = p2; acc[e][3] = p3;
        }
    }
    __syncthreads();   // srow/sg visible

    const int el = tid & 127;
    const int f4base = (tid >> 7) * 4;   // 0 or 4

    for (int c = 0; c < 4; ++c) {
        // --- stage W chunk [32k x 128] (contiguous copy) ---
        const float4* wsrc = (const float4*)(W1a + c * 32 * 128);
        float4* wdst = (float4*)Ws;
        #pragma unroll
        for (int i = 0; i < 4; ++i) wdst[tid + i * 256] = wsrc[tid + i * 256];

        // --- stage A chunk [32k x 128 edges], k-major ---
        #pragma unroll
        for (int i = 0; i < 4; ++i) {
            int fq = f4base + i;                 // float4 index 0..7 within chunk
            float4 v;
            if (c < 2) {
                const float4* src = (const float4*)(x + (long long)srow[el] * 64 + c * 32);
                v = src[fq];
            } else {
                long long e = e0 + el;
                if (e < E) {
                    const float4* src = (const float4*)(ea + e * 64 + (c - 2) * 32);
                    v = src[fq];
                } else v = make_float4(0.f, 0.f, 0.f, 0.f);
            }
            int kk = fq * 4;
            As[(kk + 0) * 128 + el] = v.x;
            As[(kk + 1) * 128 + el] = v.y;
            As[(kk + 2) * 128 + el] = v.z;
            As[(kk + 3) * 128 + el] = v.w;
        }
        __syncthreads();

        // --- mainloop: 32 k-steps, FFMA2 ---
        #pragma unroll 8
        for (int kk = 0; kk < 32; ++kk) {
            const float* ar = &As[kk * 128 + ty * 8];
            float2 a01 = *(const float2*)(ar + 0);
            float2 a23 = *(const float2*)(ar + 2);
            float2 a45 = *(const float2*)(ar + 4);
            float2 a67 = *(const float2*)(ar + 6);
            const float* wr = &Ws[kk * 128];
            unsigned long long w0 = *(const unsigned long long*)(wr + c0);
            unsigned long long w1 = *(const unsigned long long*)(wr + c0 + 2);
            unsigned long long w2 = *(const unsigned long long*)(wr + c1);
            unsigned long long w3 = *(const unsigned long long*)(wr + c1 + 2);
            unsigned long long ad[8];
            DUP2(ad[0], a01.x); DUP2(ad[1], a01.y);
            DUP2(ad[2], a23.x); DUP2(ad[3], a23.y);
            DUP2(ad[4], a45.x); DUP2(ad[5], a45.y);
            DUP2(ad[6], a67.x); DUP2(ad[7], a67.y);
            #pragma unroll
            for (int e = 0; e < 8; ++e) {
                FFMA2(acc[e][0], ad[e], w0);
                FFMA2(acc[e][1], ad[e], w1);
                FFMA2(acc[e][2], ad[e], w2);
                FFMA2(acc[e][3], ad[e], w3);
            }
        }
        __syncthreads();
    }

    // --- epilogue: leaky, scatter to graph bins, Q stats, edge counts ---
    float qc[8];
    #pragma unroll
    for (int j = 0; j < 8; ++j) qc[j] = 0.f;

    #pragma unroll
    for (int e = 0; e < 8; ++e) {
        long long eg = e0 + ty * 8 + e;
        bool valid = eg < E;
        int g = sg[ty * 8 + e];
        float z[8];
        UNPK2(z[0], z[1], acc[e][0]);
        UNPK2(z[2], z[3], acc[e][1]);
        UNPK2(z[4], z[5], acc[e][2]);
        UNPK2(z[6], z[7], acc[e][3]);
        #pragma unroll
        for (int j = 0; j < 8; ++j) {
            float a = leaky(z[j]);
            z[j] = a;
            if (valid) qc[j] += a * a;
        }
        if (valid) {
            float* base = d_A + (long long)g * 128;
            red4(base + c0, make_float4(z[0], z[1], z[2], z[3]));
            red4(base + c1, make_float4(z[4], z[5], z[6], z[7]));
            if (tx == 0) atomicAdd(&d_cnt[g], 1);
        }
    }

    // fold Q across the two ty's sharing a warp, then one red4 per lane<16
    #pragma unroll
    for (int j = 0; j < 8; ++j) qc[j] += __shfl_xor_sync(0xffffffffu, qc[j], 16);
    if ((tid & 16) == 0) {
        red4(d_Q + c0, make_float4(qc[0], qc[1], qc[2], qc[3]));
        red4(d_Q + c1, make_float4(qc[4], qc[5], qc[6], qc[7]));
    }
}

// ---------------- K2: gx[b] += x[node] ----------------
__global__ void k_gx(const float* __restrict__ x, const void* __restrict__ bat,
                     long long N) {
    long long idx = (long long)blockIdx.x * blockDim.x + threadIdx.x;
    if (idx >= N * 16) return;
    long long node = idx >> 4;
    int q = (int)(idx & 15);
    int g = (int)ldix(bat, node, d_f_b64);
    float4 v = ((const float4*)x)[node * 16 + q];
    red4(d_gx + (long long)g * 64 + q * 4, v);
}

// ---------------- K2.5: BN1a fold + t2eff = t1@W2a + b2a ----------------
__global__ void k_prep(const float* __restrict__ W2a, const float* __restrict__ b2a,
                       const float* __restrict__ g1a, const float* __restrict__ be1a,
                       float Ef, int B) {
    __shared__ float st1[128];
    int j = threadIdx.x;
    float S = 0.f;
    for (int b = 0; b < B; ++b) S += d_A[b * 128 + j];
    float m = S / Ef;
    float v = d_Q[j] / Ef - m * m;
    float s = g1a[j] * rsqrtf(v + EPS);
    float t = be1a[j] - m * s;
    d_s1[j] = s;
    st1[j] = t;
    __syncthreads();
    float a = b2a[j];
    #pragma unroll 8
    for (int k = 0; k < 128; ++k) a += st1[k] * W2a[k * 128 + j];
    d_t2[j] = a;
}

// ---------------- K3: ga + first graph layer + stats ----------------
__global__ void k_g1(const float* __restrict__ W2a,
                     const float* __restrict__ W1b, const float* __restrict__ b1b) {
    __shared__ float sAs[128], sga[128], sgx[64];
    int b = blockIdx.x, j = threadIdx.x;
    sAs[j] = d_A[b * 128 + j] * d_s1[j];
    if (j < 64) sgx[j] = d_gx[b * 64 + j];
    __syncthreads();
    float cf = (float)d_cnt[b];
    float ga = d_t2[j] * cf;
    #pragma unroll 8
    for (int k = 0; k < 128; ++k) ga += sAs[k] * W2a[k * 128 + j];
    sga[j] = ga;
    __syncthreads();
    float z = b1b[j];
    #pragma unroll 8
    for (int i = 0; i < 64; ++i)  z += sgx[i] * W1b[i * 128 + j];
    #pragma unroll 8
    for (int i = 0; i < 128; ++i) z += sga[i] * W1b[(64 + i) * 128 + j];
    float a = leaky(z);
    d_a1[b * 128 + j] = a;
    atomicAdd(&d_S1[j], a);
    atomicAdd(&d_Q1[j], a * a);
}

// ---------------- K4: BN1b + second graph layer + stats ----------------
__global__ void k_g2(const float* __restrict__ W2b, const float* __restrict__ b2b,
                     const float* __restrict__ g1b, const float* __restrict__ be1b,
                     float Bf) {
    __shared__ float sh[128];
    int b = blockIdx.x, j = threadIdx.x;
    float m = d_S1[j] / Bf;
    float v = d_Q1[j] / Bf - m * m;
    float s = g1b[j] * rsqrtf(v + EPS);
    float t = be1b[j] - m * s;
    sh[j] = d_a1[b * 128 + j] * s + t;
    __syncthreads();
    float z = b2b[j];
    #pragma unroll 8
    for (int k = 0; k < 128; ++k) z += sh[k] * W2b[k * 128 + j];
    float a = leaky(z);
    d_a2[b * 128 + j] = a;
    atomicAdd(&d_S2[j], a);
    atomicAdd(&d_Q2[j], a * a);
}

// ---------------- K5: BN2b + output layer ----------------
__global__ void k_g3(const float* __restrict__ W3b, const float* __restrict__ b3b,
                     const float* __restrict__ g2b, const float* __restrict__ be2b,
                     float Bf, float* __restrict__ out) {
    __shared__ float sh[128];
    int b = blockIdx.x, j = threadIdx.x;
    float m = d_S2[j] / Bf;
    float v = d_Q2[j] / Bf - m * m;
    float s = g2b[j] * rsqrtf(v + EPS);
    float t = be2b[j] - m * s;
    sh[j] = d_a2[b * 128 + j] * s + t;
    __syncthreads();
    float z = b3b[j];
    #pragma unroll 8
    for (int k = 0; k < 128; ++k) z += sh[k] * W3b[k * 128 + j];
    out[b * 128 + j] = z;
}

// ---------------- launch ----------------
extern "C" void kernel_launch(void* const* d_in, const int* in_sizes, int n_in,
                              void* d_out, int out_size) {
    const float* x    = (const float*)d_in[0];
    const void*  ei   = d_in[1];
    const float* ea   = (const float*)d_in[2];
    const void*  bat  = d_in[4];
    const float* W1a  = (const float*)d_in[5];
    const float* b1a  = (const float*)d_in[6];
    const float* g1a  = (const float*)d_in[7];
    const float* be1a = (const float*)d_in[8];
    const float* W2a  = (const float*)d_in[9];
    const float* b2a  = (const float*)d_in[10];
    const float* W1b  = (const float*)d_in[11];
    const float* b1b  = (const float*)d_in[12];
    const float* g1b  = (const float*)d_in[13];
    const float* be1b = (const float*)d_in[14];
    const float* W2b  = (const float*)d_in[15];
    const float* b2b  = (const float*)d_in[16];
    const float* g2b  = (const float*)d_in[17];
    const float* be2b = (const float*)d_in[18];
    const float* W3b  = (const float*)d_in[19];
    const float* b3b  = (const float*)d_in[20];

    long long N = (long long)in_sizes[0] / 64;
    long long E = (long long)in_sizes[2] / 64;
    int B = in_sizes[3];
    if (B > MAXB) B = MAXB;

    k_init<<<256, 256>>>(ei, bat, 2 * E, N);

    int gridE = (int)((E + 127) / 128);
    k_edge<<<gridE, 256>>>(x, ei, ea, bat, W1a, b1a, E);

    int gridN = (int)((N * 16 + 255) / 256);
    k_gx<<<gridN, 256>>>(x, bat, N);

    k_prep<<<1, 128>>>(W2a, b2a, g1a, be1a, (float)E, B);
    k_g1<<<B, 128>>>(W2a, W1b, b1b);
    k_g2<<<B, 128>>>(W2b, b2b, g1b, be1b, (float)B);
    k_g3<<<B, 128>>>(W3b, b3b, g2b, be2b, (float)B, (float*)d_out);
}